// round 15
// baseline (speedup 1.0000x reference)
#include <cuda_runtime.h>
#include <cuda_bf16.h>

// HMM forward, time-parallel 3-phase decomposition (R15).
// = R14 + (a) mid_kernel preloads ALL 14 matrix slots (MLP 4 -> 14),
//         (b) prep_bits via smem transpose instead of 32 serialized ballots.
// pass1/pass2 byte-identical to the passing 124.9us R14.

#define TT   512
#define NSEQ 16384
#define KM   14
#define MAXV 8192
#define LN2f 0.69314718055994530942f
#define L2Ef 1.44269504088896340736f

typedef unsigned long long ull;

__device__ uint2    g_BtH[MAXV];          // bf16x4 linear emissions per token
__device__ __align__(16) float g_Wc[12];  // exp(A) x8 + logpi x4
__device__ unsigned g_mb[NSEQ * 16];      // mask bits: word (seq,k), bit j = (m[t]==1)
__device__ float4   g_M [KM * 4 * NSEQ];  // chunk matrices [k-1][row][seq]
__device__ float    g_Mc[KM * NSEQ];      // chunk matrix log offsets
__device__ float4   g_S [16 * NSEQ];      // g_S[0]=alpha0; g_S[k]=alpha(32k-1)

struct W8 { float AEB, ASB, ABM, AMM, ABE, AME, AES, ASS; };

__device__ __forceinline__ W8 load_wc() {
    float4 a = *(const float4*)&g_Wc[0];
    float4 b = *(const float4*)&g_Wc[4];
    W8 w;
    w.AEB = a.x; w.ASB = a.y; w.ABM = a.z; w.AMM = a.w;
    w.ABE = b.x; w.AME = b.y; w.AES = b.z; w.ASS = b.w;
    return w;
}

__device__ __forceinline__ void unp(uint2 v, float& e0, float& e1, float& e2, float& e3) {
    e0 = __uint_as_float(v.x << 16);
    e1 = __uint_as_float(v.x & 0xFFFF0000u);
    e2 = __uint_as_float(v.y << 16);
    e3 = __uint_as_float(v.y & 0xFFFF0000u);
}

// ---- packed f32x2 helpers ----
__device__ __forceinline__ ull pk(float a, float b) {
    ull r; asm("mov.b64 %0, {%1, %2};" : "=l"(r) : "f"(a), "f"(b)); return r;
}
__device__ __forceinline__ ull pk2(float a) { return pk(a, a); }
__device__ __forceinline__ void upk(ull v, float& a, float& b) {
    asm("mov.b64 {%0, %1}, %2;" : "=f"(a), "=f"(b) : "l"(v));
}
__device__ __forceinline__ ull mul2(ull a, ull b) {
    ull r; asm("mul.rn.f32x2 %0, %1, %2;" : "=l"(r) : "l"(a), "l"(b)); return r;
}
__device__ __forceinline__ ull fma2(ull a, ull b, ull c) {
    ull r; asm("fma.rn.f32x2 %0, %1, %2, %3;" : "=l"(r) : "l"(a), "l"(b), "l"(c)); return r;
}

// ---------------- prep: bf16x4 emission table + weights ----------------
__global__ void prep_kernel(const float* __restrict__ logB,
                            const float* __restrict__ logA,
                            const float* __restrict__ logpi, int NV) {
    if (blockIdx.x == 0 && threadIdx.x < 12) {
        const int map[8] = {8, 12, 1, 5, 2, 6, 11, 15};
        if (threadIdx.x < 8) g_Wc[threadIdx.x] = expf(logA[map[threadIdx.x]]);
        else                 g_Wc[threadIdx.x] = logpi[threadIdx.x - 8];
    }
    int i = blockIdx.x * blockDim.x + threadIdx.x;
    if (i >= NV) return;
    unsigned b0 = (unsigned)__bfloat16_as_ushort(__float2bfloat16(expf(logB[i])));
    unsigned b1 = (unsigned)__bfloat16_as_ushort(__float2bfloat16(expf(logB[NV + i])));
    unsigned b2 = (unsigned)__bfloat16_as_ushort(__float2bfloat16(expf(logB[2 * NV + i])));
    unsigned b3 = (unsigned)__bfloat16_as_ushort(__float2bfloat16(expf(logB[3 * NV + i])));
    uint2 v; v.x = b0 | (b1 << 16); v.y = b2 | (b3 << 16);
    g_BtH[i] = v;
}

// ---------------- prep_bits: mask -> 1 bit per (seq,t) ----------------
// Per warp-tile: 32 seqs x 32 t. Coalesced loads into padded smem, then each
// lane packs its own seq's 32 bits from conflict-free LDS (no serialized
// ballots). Output identical to the ballot version.
__global__ __launch_bounds__(256) void prep_bits_kernel(const float* __restrict__ mask, int N)
{
    __shared__ float buf[8][32 * 33];
    int tile = blockIdx.x * 8 + (threadIdx.x >> 5);
    int lane = threadIdx.x & 31;
    int w    = threadIdx.x >> 5;
    if (tile >= (N / 32) * 16) return;
    int seq0 = (tile >> 4) * 32;
    int tc   = tile & 15;
    const float* mp = mask + (size_t)seq0 * TT + tc * 32 + lane;
#pragma unroll 8
    for (int q = 0; q < 32; q++)
        buf[w][q * 33 + lane] = __ldg(mp + (size_t)q * TT);
    __syncwarp();
    unsigned bits = 0;
#pragma unroll
    for (int j = 0; j < 32; j++)
        bits |= (buf[w][lane * 33 + j] == 1.0f ? 1u : 0u) << j;
    g_mb[(size_t)(seq0 + lane) * 16 + tc] = bits;
}

// ---------------- pass1: chunk0 alphas (k=0) + transfer matrices (k=1..14) --
// block = 256 threads, k uniform per block; warp = 32 consecutive seqs.
// smem: bf16 table + per-warp u16 Y staging (stride-17 words, conflict-free).
__global__ __launch_bounds__(256, 3) void pass1_kernel(
    const int* __restrict__ Y, const float* __restrict__ logB, int N, int NV)
{
    extern __shared__ char sm1[];
    uint2* s_tab1 = (uint2*)sm1;
    unsigned* ysall = (unsigned*)(sm1 + (size_t)NV * 8);
    for (int i = threadIdx.x; i < NV; i += 256) s_tab1[i] = g_BtH[i];
    __syncthreads();

    const int tid = threadIdx.x, lane = tid & 31, wid = tid >> 5;
    int tau = blockIdx.x * 256 + tid;
    int k   = tau / N;                  // uniform per block (N % 256 == 0)
    int seq = tau - k * N;
    int seqb = seq - lane;              // warp's first seq
    unsigned* ys = ysall + wid * 544;

    // stage warp's 32 seqs x 32 t of Y, coalesced (4 rows / instruction)
#pragma unroll
    for (int i = 0; i < 8; i++) {
        int r = i * 4 + (lane >> 3);
        int4 yv = __ldg((const int4*)(Y + (size_t)(seqb + r) * TT + 32 * k) + (lane & 7));
        ys[r * 17 + 2 * (lane & 7)]     = (unsigned)yv.x | ((unsigned)yv.y << 16);
        ys[r * 17 + 2 * (lane & 7) + 1] = (unsigned)yv.z | ((unsigned)yv.w << 16);
    }
    __syncwarp();
    const unsigned* ysr = ys + lane * 17;   // this thread's 16 packed words

    W8 w = load_wc();
    unsigned mb = g_mb[(size_t)seq * 16 + k];

    if (k == 0) {
        // exact alpha0 (divergent gathers, once); logpi from g_Wc[8..11]
        int y0 = (int)(ysr[0] & 0xFFFFu);
        float a0 = g_Wc[8]  + __ldg(&logB[y0]);
        float a1 = g_Wc[9]  + __ldg(&logB[NV + y0]);
        float a2 = g_Wc[10] + __ldg(&logB[2 * NV + y0]);
        float a3 = g_Wc[11] + __ldg(&logB[3 * NV + y0]);
        g_S[seq] = make_float4(a0, a1, a2, a3);
        float c = fmaxf(fmaxf(a0, a1), fmaxf(a2, a3));
        float p0 = exp2f((a0 - c) * L2Ef), p1 = exp2f((a1 - c) * L2Ef);
        float p2 = exp2f((a2 - c) * L2Ef), p3 = exp2f((a3 - c) * L2Ef);

#pragma unroll 1
        for (int jj = 0; jj < 8; jj++) {
            unsigned w0 = ysr[jj * 2], w1 = ysr[jj * 2 + 1];
            uint2 evs[4];
            evs[0] = s_tab1[w0 & 0xFFFFu]; evs[1] = s_tab1[w0 >> 16];
            evs[2] = s_tab1[w1 & 0xFFFFu]; evs[3] = s_tab1[w1 >> 16];
#pragma unroll
            for (int q = 0; q < 4; q++) {
                int j = jj * 4 + q;
                if (j != 0 && ((mb >> j) & 1u)) {
                    float e0, e1, e2, e3; unp(evs[q], e0, e1, e2, e3);
                    float qB = e0 * fmaf(w.ASB, p3, w.AEB * p2);
                    float qM = e1 * fmaf(w.AMM, p1, w.ABM * p0);
                    float qE = e2 * fmaf(w.AME, p1, w.ABE * p0);
                    float qS = e3 * fmaf(w.ASS, p3, w.AES * p2);
                    p0 = qB; p1 = qM; p2 = qE; p3 = qS;
                }
            }
            float mx = fmaxf(fmaxf(p0, p1), fmaxf(p2, p3));
            int eb = __float_as_int(mx) >> 23;
            float sc = __int_as_float((254 - eb) << 23);
            c = fmaf((float)(eb - 127), LN2f, c);
            p0 *= sc; p1 *= sc; p2 *= sc; p3 *= sc;
        }
        g_S[N + seq] = make_float4(fmaf(__log2f(p0), LN2f, c), fmaf(__log2f(p1), LN2f, c),
                                   fmaf(__log2f(p2), LN2f, c), fmaf(__log2f(p3), LN2f, c));
        return;
    }

    // transfer matrix for chunk k (packed f32x2 rows); bit=0 -> identity (m=0)
    ull R0a = pk(1.f, 0.f), R0b = pk(0.f, 0.f);   // row B
    ull R1a = pk(0.f, 1.f), R1b = pk(0.f, 0.f);   // row M
    ull R2a = pk(0.f, 0.f), R2b = pk(1.f, 0.f);   // row E
    ull R3a = pk(0.f, 0.f), R3b = pk(0.f, 1.f);   // row S
    float c = 0.f;

#pragma unroll 1
    for (int jj = 0; jj < 8; jj++) {
        unsigned w0 = ysr[jj * 2], w1 = ysr[jj * 2 + 1];
        uint2 evs[4];
        evs[0] = s_tab1[w0 & 0xFFFFu]; evs[1] = s_tab1[w0 >> 16];
        evs[2] = s_tab1[w1 & 0xFFFFu]; evs[3] = s_tab1[w1 >> 16];
#pragma unroll
        for (int q = 0; q < 4; q++) {
            if ((mb >> (jj * 4 + q)) & 1u) {
                float e0, e1, e2, e3; unp(evs[q], e0, e1, e2, e3);
                ull U0 = pk2(e0 * w.AEB), V0 = pk2(e0 * w.ASB);
                ull U1 = pk2(e1 * w.ABM), V1 = pk2(e1 * w.AMM);
                ull U2 = pk2(e2 * w.ABE), V2 = pk2(e2 * w.AME);
                ull U3 = pk2(e3 * w.AES), V3 = pk2(e3 * w.ASS);
                ull nBa = fma2(V0, R3a, mul2(U0, R2a));
                ull nBb = fma2(V0, R3b, mul2(U0, R2b));
                ull nSa = fma2(V3, R3a, mul2(U3, R2a));
                ull nSb = fma2(V3, R3b, mul2(U3, R2b));
                ull nMa = fma2(V1, R1a, mul2(U1, R0a));
                ull nMb = fma2(V1, R1b, mul2(U1, R0b));
                ull nEa = fma2(V2, R1a, mul2(U2, R0a));
                ull nEb = fma2(V2, R1b, mul2(U2, R0b));
                R0a = nBa; R0b = nBb; R1a = nMa; R1b = nMb;
                R2a = nEa; R2b = nEb; R3a = nSa; R3b = nSb;
            }
        }
        float f0, f1, f2, f3, f4, f5, f6, f7, g0, g1, g2, g3, g4, g5, g6, g7;
        upk(R0a, f0, f1); upk(R0b, f2, f3); upk(R1a, f4, f5); upk(R1b, f6, f7);
        upk(R2a, g0, g1); upk(R2b, g2, g3); upk(R3a, g4, g5); upk(R3b, g6, g7);
        float mx = fmaxf(fmaxf(fmaxf(fmaxf(f0, f1), fmaxf(f2, f3)),
                               fmaxf(fmaxf(f4, f5), fmaxf(f6, f7))),
                         fmaxf(fmaxf(fmaxf(g0, g1), fmaxf(g2, g3)),
                               fmaxf(fmaxf(g4, g5), fmaxf(g6, g7))));
        int eb = __float_as_int(mx) >> 23;
        float sc = __int_as_float((254 - eb) << 23);
        c = fmaf((float)(eb - 127), LN2f, c);
        ull SC = pk2(sc);
        R0a = mul2(R0a, SC); R0b = mul2(R0b, SC);
        R1a = mul2(R1a, SC); R1b = mul2(R1b, SC);
        R2a = mul2(R2a, SC); R2b = mul2(R2b, SC);
        R3a = mul2(R3a, SC); R3b = mul2(R3b, SC);
    }
    float f0, f1, f2, f3;
    int b = ((k - 1) * 4) * N + seq;
    upk(R0a, f0, f1); upk(R0b, f2, f3); g_M[b]         = make_float4(f0, f1, f2, f3);
    upk(R1a, f0, f1); upk(R1b, f2, f3); g_M[b + N]     = make_float4(f0, f1, f2, f3);
    upk(R2a, f0, f1); upk(R2b, f2, f3); g_M[b + 2 * N] = make_float4(f0, f1, f2, f3);
    upk(R3a, f0, f1); upk(R3b, f2, f3); g_M[b + 3 * N] = make_float4(f0, f1, f2, f3);
    g_Mc[(k - 1) * N + seq] = c;
}

// ---------------- middle: compose 14 matvecs, 4 threads/seq, full preload ---
// thread = (seq, row). ALL 14 row/cm slots loaded up front (MLP=14+), then a
// pure compute chain: dot, shfl exchange, rescale, per-row log output.
__global__ __launch_bounds__(128) void mid_kernel(int N)
{
    int gt = blockIdx.x * 128 + threadIdx.x;
    if (gt >= 4 * N) return;
    const int seq = gt >> 2, row = gt & 3;
    const int gbase = (threadIdx.x & 31) & ~3;

    float4 RV[KM]; float CM[KM];
#pragma unroll
    for (int k = 1; k <= KM; k++) {
        RV[k - 1] = __ldg(&g_M[(size_t)((k - 1) * 4 + row) * N + seq]);
        CM[k - 1] = __ldg(&g_Mc[(size_t)(k - 1) * N + seq]);
    }

    float4 a = __ldg(&g_S[N + seq]);
    float c = fmaxf(fmaxf(a.x, a.y), fmaxf(a.z, a.w));
    float p0 = exp2f((a.x - c) * L2Ef), p1 = exp2f((a.y - c) * L2Ef);
    float p2 = exp2f((a.z - c) * L2Ef), p3 = exp2f((a.w - c) * L2Ef);

#pragma unroll
    for (int k = 1; k <= KM; k++) {
        float4 rv = RV[k - 1]; float cm = CM[k - 1];

        float q = fmaf(rv.x, p0, fmaf(rv.y, p1, fmaf(rv.z, p2, rv.w * p3)));
        float outv = fmaf(__log2f(q), LN2f, c + cm);     // own-row output, exact

        float q0 = __shfl_sync(0xFFFFFFFFu, q, gbase + 0);
        float q1 = __shfl_sync(0xFFFFFFFFu, q, gbase + 1);
        float q2 = __shfl_sync(0xFFFFFFFFu, q, gbase + 2);
        float q3 = __shfl_sync(0xFFFFFFFFu, q, gbase + 3);
        c += cm;
        float mx = fmaxf(fmaxf(q0, q1), fmaxf(q2, q3));
        int eb = __float_as_int(mx) >> 23;
        float sc = __int_as_float((254 - eb) << 23);
        c = fmaf((float)(eb - 127), LN2f, c);
        p0 = q0 * sc; p1 = q1 * sc; p2 = q2 * sc; p3 = q3 * sc;

        ((float*)g_S)[(size_t)(k + 1) * N * 4 + (size_t)seq * 4 + row] = outv;
    }
}

// ---------------- pass2: emit all alphas -----------------------------------
// block = 256 = 16 seqs x 16 chunks; warp = 2 seqs x 16 chunks.
// smem: bf16 table + per-warp u16 Y staging (stride-17 words, conflict-free).
__global__ __launch_bounds__(256, 3) void pass2_kernel(
    const int* __restrict__ Y, const float* __restrict__ mask,
    float* __restrict__ out, int N, int NV)
{
    extern __shared__ char sm2[];
    uint2* tab = (uint2*)sm2;
    unsigned* ysall = (unsigned*)(sm2 + (size_t)NV * 8);
    for (int i = threadIdx.x; i < NV; i += 256) tab[i] = g_BtH[i];
    __syncthreads();

    const int tid = threadIdx.x, lane = tid & 31, wid = tid >> 5;
    const int bseq = blockIdx.x * 16;
    const int seq  = bseq + (tid >> 4);
    const int k    = tid & 15;
    const int seqL = (tid >> 4) & 1;
    unsigned* ys = ysall + wid * 544;

    // stage Y (warp's 2 seqs x 512 t) as packed u16 pairs, coalesced loads
    {
        int sp0 = bseq + (wid << 1);
#pragma unroll
        for (int i = 0; i < 8; i++) {
            int sL = i >> 2, tb = (i & 3) * 128;
            int4 yv = __ldg((const int4*)(Y + (size_t)(sp0 + sL) * TT + tb) + lane);
            int kk = (i & 3) * 4 + (lane >> 3);
            int u2 = (lane & 7) * 2;
            ys[sL * 272 + kk * 17 + u2]     = (unsigned)yv.x | ((unsigned)yv.y << 16);
            ys[sL * 272 + kk * 17 + u2 + 1] = (unsigned)yv.z | ((unsigned)yv.w << 16);
        }
    }
    __syncwarp();

    W8 w = load_wc();
    unsigned mb = g_mb[(size_t)bseq * 16 + tid];   // == g_mb[seq*16 + k]

    float4 a = __ldg(&g_S[k * N + seq]);           // exact start (alpha0 for k=0)
    float ap0 = a.x, ap1 = a.y, ap2 = a.z, ap3 = a.w;
    float c  = fmaxf(fmaxf(ap0, ap1), fmaxf(ap2, ap3));
    float p0 = exp2f((ap0 - c) * L2Ef), p1 = exp2f((ap1 - c) * L2Ef);
    float p2 = exp2f((ap2 - c) * L2Ef), p3 = exp2f((ap3 - c) * L2Ef);

    const unsigned* ysk = ys + seqL * 272 + k * 17;
    float* rowp = out + (size_t)seq * (4 * TT) + k * 32;

#pragma unroll 1
    for (int g = 0; g < 4; g++) {
        float4 an[8];
#pragma unroll
        for (int h = 0; h < 2; h++) {
            int j0 = g * 8 + h * 4;
            unsigned w0 = ysk[(j0 >> 1)];
            unsigned w1 = ysk[(j0 >> 1) + 1];
            uint2 evs[4];
            evs[0] = tab[w0 & 0xFFFFu]; evs[1] = tab[w0 >> 16];
            evs[2] = tab[w1 & 0xFFFFu]; evs[3] = tab[w1 >> 16];
#pragma unroll
            for (int q = 0; q < 4; q++) {
                int j = j0 + q;
                if (k == 0 && j == 0 && g == 0) {
                    an[0] = make_float4(ap0, ap1, ap2, ap3);   // t=0 exact
                } else {
                    float e0, e1, e2, e3; unp(evs[q], e0, e1, e2, e3);
                    float qB = e0 * fmaf(w.ASB, p3, w.AEB * p2);
                    float qM = e1 * fmaf(w.AMM, p1, w.ABM * p0);
                    float qE = e2 * fmaf(w.AME, p1, w.ABE * p0);
                    float qS = e3 * fmaf(w.ASS, p3, w.AES * p2);
                    float n0 = fmaf(__log2f(qB), LN2f, c);
                    float n1 = fmaf(__log2f(qM), LN2f, c);
                    float n2 = fmaf(__log2f(qE), LN2f, c);
                    float n3 = fmaf(__log2f(qS), LN2f, c);
                    if ((mb >> j) & 1u) {
                        p0 = qB; p1 = qM; p2 = qE; p3 = qS;
                        if (q == 3) {
                            float mx = fmaxf(fmaxf(p0, p1), fmaxf(p2, p3));
                            int eb = __float_as_int(mx) >> 23;
                            float sc = __int_as_float((254 - eb) << 23);
                            c = fmaf((float)(eb - 127), LN2f, c);
                            p0 *= sc; p1 *= sc; p2 *= sc; p3 *= sc;
                        }
                    } else {
                        // rare general path: fetch float mask, exact blend
                        float m = __ldg(&mask[(size_t)seq * TT + k * 32 + j]);
                        n0 = fmaf(m, n0 - ap0, ap0);
                        n1 = fmaf(m, n1 - ap1, ap1);
                        n2 = fmaf(m, n2 - ap2, ap2);
                        n3 = fmaf(m, n3 - ap3, ap3);
                        c  = fmaxf(fmaxf(n0, n1), fmaxf(n2, n3));
                        p0 = exp2f((n0 - c) * L2Ef); p1 = exp2f((n1 - c) * L2Ef);
                        p2 = exp2f((n2 - c) * L2Ef); p3 = exp2f((n3 - c) * L2Ef);
                    }
                    ap0 = n0; ap1 = n1; ap2 = n2; ap3 = n3;
                    an[j - g * 8] = make_float4(n0, n1, n2, n3);
                }
            }
        }
        // direct stores: per state a full 32B sector (two aligned STG.128)
        float* gp = rowp + g * 8;
        *(float4*)(gp)               = make_float4(an[0].x, an[1].x, an[2].x, an[3].x);
        *(float4*)(gp + 4)           = make_float4(an[4].x, an[5].x, an[6].x, an[7].x);
        *(float4*)(gp + TT)          = make_float4(an[0].y, an[1].y, an[2].y, an[3].y);
        *(float4*)(gp + TT + 4)      = make_float4(an[4].y, an[5].y, an[6].y, an[7].y);
        *(float4*)(gp + 2 * TT)      = make_float4(an[0].z, an[1].z, an[2].z, an[3].z);
        *(float4*)(gp + 2 * TT + 4)  = make_float4(an[4].z, an[5].z, an[6].z, an[7].z);
        *(float4*)(gp + 3 * TT)      = make_float4(an[0].w, an[1].w, an[2].w, an[3].w);
        *(float4*)(gp + 3 * TT + 4)  = make_float4(an[4].w, an[5].w, an[6].w, an[7].w);
    }
}

extern "C" void kernel_launch(void* const* d_in, const int* in_sizes, int n_in,
                              void* d_out, int out_size) {
    const int*   Y     = (const int*)  d_in[0];
    const float* mask  = (const float*)d_in[1];
    const float* logpi = (const float*)d_in[2];
    const float* logA  = (const float*)d_in[3];
    const float* logB  = (const float*)d_in[4];
    float*       out   = (float*)d_out;

    const int N  = in_sizes[0] / TT;
    const int NV = in_sizes[4] / 4;

    const int smem1 = NV * 8 + 8 * 544 * 4;         // 65408 B (table + Y staging)
    const int smem2 = NV * 8 + 8 * 544 * 4;         // 65408 B (table + Y staging)

    cudaFuncSetAttribute(pass1_kernel, cudaFuncAttributeMaxDynamicSharedMemorySize, smem1);
    cudaFuncSetAttribute(pass2_kernel, cudaFuncAttributeMaxDynamicSharedMemorySize, smem2);

    prep_kernel<<<(NV + 255) / 256, 256>>>(logB, logA, logpi, NV);
    prep_bits_kernel<<<N / 16, 256>>>(mask, N);
    pass1_kernel<<<((KM + 1) * N + 255) / 256, 256, smem1>>>(Y, logB, N, NV);
    mid_kernel<<<(4 * N + 127) / 128, 128>>>(N);
    pass2_kernel<<<N / 16, 256, smem2>>>(Y, mask, out, N, NV);
}

// round 16
// speedup vs baseline: 1.0304x; 1.0304x over previous
#include <cuda_runtime.h>
#include <cuda_bf16.h>

// HMM forward, time-parallel 3-phase decomposition (R16).
// = R14 (verified 124.9us) + mid_kernel preload PINNED via inline asm so
// ptxas cannot sink the 14 slot loads (R12/R15 both showed it discarding
// source-level prefetch to save registers).

#define TT   512
#define NSEQ 16384
#define KM   14
#define MAXV 8192
#define LN2f 0.69314718055994530942f
#define L2Ef 1.44269504088896340736f

typedef unsigned long long ull;

__device__ uint2    g_BtH[MAXV];          // bf16x4 linear emissions per token
__device__ __align__(16) float g_Wc[12];  // exp(A) x8 + logpi x4
__device__ unsigned g_mb[NSEQ * 16];      // mask bits: word (seq,k), bit j = (m[t]==1)
__device__ float4   g_M [KM * 4 * NSEQ];  // chunk matrices [k-1][row][seq]
__device__ float    g_Mc[KM * NSEQ];      // chunk matrix log offsets
__device__ float4   g_S [16 * NSEQ];      // g_S[0]=alpha0; g_S[k]=alpha(32k-1)

struct W8 { float AEB, ASB, ABM, AMM, ABE, AME, AES, ASS; };

__device__ __forceinline__ W8 load_wc() {
    float4 a = *(const float4*)&g_Wc[0];
    float4 b = *(const float4*)&g_Wc[4];
    W8 w;
    w.AEB = a.x; w.ASB = a.y; w.ABM = a.z; w.AMM = a.w;
    w.ABE = b.x; w.AME = b.y; w.AES = b.z; w.ASS = b.w;
    return w;
}

__device__ __forceinline__ void unp(uint2 v, float& e0, float& e1, float& e2, float& e3) {
    e0 = __uint_as_float(v.x << 16);
    e1 = __uint_as_float(v.x & 0xFFFF0000u);
    e2 = __uint_as_float(v.y << 16);
    e3 = __uint_as_float(v.y & 0xFFFF0000u);
}

// ---- packed f32x2 helpers ----
__device__ __forceinline__ ull pk(float a, float b) {
    ull r; asm("mov.b64 %0, {%1, %2};" : "=l"(r) : "f"(a), "f"(b)); return r;
}
__device__ __forceinline__ ull pk2(float a) { return pk(a, a); }
__device__ __forceinline__ void upk(ull v, float& a, float& b) {
    asm("mov.b64 {%0, %1}, %2;" : "=f"(a), "=f"(b) : "l"(v));
}
__device__ __forceinline__ ull mul2(ull a, ull b) {
    ull r; asm("mul.rn.f32x2 %0, %1, %2;" : "=l"(r) : "l"(a), "l"(b)); return r;
}
__device__ __forceinline__ ull fma2(ull a, ull b, ull c) {
    ull r; asm("fma.rn.f32x2 %0, %1, %2, %3;" : "=l"(r) : "l"(a), "l"(b), "l"(c)); return r;
}

// ---------------- prep: bf16x4 emission table + weights ----------------
__global__ void prep_kernel(const float* __restrict__ logB,
                            const float* __restrict__ logA,
                            const float* __restrict__ logpi, int NV) {
    if (blockIdx.x == 0 && threadIdx.x < 12) {
        const int map[8] = {8, 12, 1, 5, 2, 6, 11, 15};
        if (threadIdx.x < 8) g_Wc[threadIdx.x] = expf(logA[map[threadIdx.x]]);
        else                 g_Wc[threadIdx.x] = logpi[threadIdx.x - 8];
    }
    int i = blockIdx.x * blockDim.x + threadIdx.x;
    if (i >= NV) return;
    unsigned b0 = (unsigned)__bfloat16_as_ushort(__float2bfloat16(expf(logB[i])));
    unsigned b1 = (unsigned)__bfloat16_as_ushort(__float2bfloat16(expf(logB[NV + i])));
    unsigned b2 = (unsigned)__bfloat16_as_ushort(__float2bfloat16(expf(logB[2 * NV + i])));
    unsigned b3 = (unsigned)__bfloat16_as_ushort(__float2bfloat16(expf(logB[3 * NV + i])));
    uint2 v; v.x = b0 | (b1 << 16); v.y = b2 | (b3 << 16);
    g_BtH[i] = v;
}

// ---------------- prep_bits: mask -> 1 bit per (seq,t) ----------------
__global__ __launch_bounds__(256) void prep_bits_kernel(const float* __restrict__ mask, int N)
{
    int tile = blockIdx.x * 8 + (threadIdx.x >> 5);
    int lane = threadIdx.x & 31;
    if (tile >= (N / 32) * 16) return;
    int seq0 = (tile >> 4) * 32;
    int tc   = tile & 15;
    const float* mp = mask + (size_t)seq0 * TT + tc * 32 + lane;
    unsigned w = 0;
#pragma unroll 4
    for (int q = 0; q < 32; q++) {
        float m = __ldg(mp + (size_t)q * TT);
        unsigned b = __ballot_sync(0xFFFFFFFFu, m == 1.0f);
        if (lane == q) w = b;
    }
    g_mb[(size_t)(seq0 + lane) * 16 + tc] = w;
}

// ---------------- pass1: chunk0 alphas (k=0) + transfer matrices (k=1..14) --
// block = 256 threads, k uniform per block; warp = 32 consecutive seqs.
// smem: bf16 table + per-warp u16 Y staging (stride-17 words, conflict-free).
__global__ __launch_bounds__(256, 3) void pass1_kernel(
    const int* __restrict__ Y, const float* __restrict__ logB, int N, int NV)
{
    extern __shared__ char sm1[];
    uint2* s_tab1 = (uint2*)sm1;
    unsigned* ysall = (unsigned*)(sm1 + (size_t)NV * 8);
    for (int i = threadIdx.x; i < NV; i += 256) s_tab1[i] = g_BtH[i];
    __syncthreads();

    const int tid = threadIdx.x, lane = tid & 31, wid = tid >> 5;
    int tau = blockIdx.x * 256 + tid;
    int k   = tau / N;                  // uniform per block (N % 256 == 0)
    int seq = tau - k * N;
    int seqb = seq - lane;              // warp's first seq
    unsigned* ys = ysall + wid * 544;

    // stage warp's 32 seqs x 32 t of Y, coalesced (4 rows / instruction)
#pragma unroll
    for (int i = 0; i < 8; i++) {
        int r = i * 4 + (lane >> 3);
        int4 yv = __ldg((const int4*)(Y + (size_t)(seqb + r) * TT + 32 * k) + (lane & 7));
        ys[r * 17 + 2 * (lane & 7)]     = (unsigned)yv.x | ((unsigned)yv.y << 16);
        ys[r * 17 + 2 * (lane & 7) + 1] = (unsigned)yv.z | ((unsigned)yv.w << 16);
    }
    __syncwarp();
    const unsigned* ysr = ys + lane * 17;   // this thread's 16 packed words

    W8 w = load_wc();
    unsigned mb = g_mb[(size_t)seq * 16 + k];

    if (k == 0) {
        // exact alpha0 (divergent gathers, once); logpi from g_Wc[8..11]
        int y0 = (int)(ysr[0] & 0xFFFFu);
        float a0 = g_Wc[8]  + __ldg(&logB[y0]);
        float a1 = g_Wc[9]  + __ldg(&logB[NV + y0]);
        float a2 = g_Wc[10] + __ldg(&logB[2 * NV + y0]);
        float a3 = g_Wc[11] + __ldg(&logB[3 * NV + y0]);
        g_S[seq] = make_float4(a0, a1, a2, a3);
        float c = fmaxf(fmaxf(a0, a1), fmaxf(a2, a3));
        float p0 = exp2f((a0 - c) * L2Ef), p1 = exp2f((a1 - c) * L2Ef);
        float p2 = exp2f((a2 - c) * L2Ef), p3 = exp2f((a3 - c) * L2Ef);

#pragma unroll 1
        for (int jj = 0; jj < 8; jj++) {
            unsigned w0 = ysr[jj * 2], w1 = ysr[jj * 2 + 1];
            uint2 evs[4];
            evs[0] = s_tab1[w0 & 0xFFFFu]; evs[1] = s_tab1[w0 >> 16];
            evs[2] = s_tab1[w1 & 0xFFFFu]; evs[3] = s_tab1[w1 >> 16];
#pragma unroll
            for (int q = 0; q < 4; q++) {
                int j = jj * 4 + q;
                if (j != 0 && ((mb >> j) & 1u)) {
                    float e0, e1, e2, e3; unp(evs[q], e0, e1, e2, e3);
                    float qB = e0 * fmaf(w.ASB, p3, w.AEB * p2);
                    float qM = e1 * fmaf(w.AMM, p1, w.ABM * p0);
                    float qE = e2 * fmaf(w.AME, p1, w.ABE * p0);
                    float qS = e3 * fmaf(w.ASS, p3, w.AES * p2);
                    p0 = qB; p1 = qM; p2 = qE; p3 = qS;
                }
            }
            float mx = fmaxf(fmaxf(p0, p1), fmaxf(p2, p3));
            int eb = __float_as_int(mx) >> 23;
            float sc = __int_as_float((254 - eb) << 23);
            c = fmaf((float)(eb - 127), LN2f, c);
            p0 *= sc; p1 *= sc; p2 *= sc; p3 *= sc;
        }
        g_S[N + seq] = make_float4(fmaf(__log2f(p0), LN2f, c), fmaf(__log2f(p1), LN2f, c),
                                   fmaf(__log2f(p2), LN2f, c), fmaf(__log2f(p3), LN2f, c));
        return;
    }

    // transfer matrix for chunk k (packed f32x2 rows); bit=0 -> identity (m=0)
    ull R0a = pk(1.f, 0.f), R0b = pk(0.f, 0.f);   // row B
    ull R1a = pk(0.f, 1.f), R1b = pk(0.f, 0.f);   // row M
    ull R2a = pk(0.f, 0.f), R2b = pk(1.f, 0.f);   // row E
    ull R3a = pk(0.f, 0.f), R3b = pk(0.f, 1.f);   // row S
    float c = 0.f;

#pragma unroll 1
    for (int jj = 0; jj < 8; jj++) {
        unsigned w0 = ysr[jj * 2], w1 = ysr[jj * 2 + 1];
        uint2 evs[4];
        evs[0] = s_tab1[w0 & 0xFFFFu]; evs[1] = s_tab1[w0 >> 16];
        evs[2] = s_tab1[w1 & 0xFFFFu]; evs[3] = s_tab1[w1 >> 16];
#pragma unroll
        for (int q = 0; q < 4; q++) {
            if ((mb >> (jj * 4 + q)) & 1u) {
                float e0, e1, e2, e3; unp(evs[q], e0, e1, e2, e3);
                ull U0 = pk2(e0 * w.AEB), V0 = pk2(e0 * w.ASB);
                ull U1 = pk2(e1 * w.ABM), V1 = pk2(e1 * w.AMM);
                ull U2 = pk2(e2 * w.ABE), V2 = pk2(e2 * w.AME);
                ull U3 = pk2(e3 * w.AES), V3 = pk2(e3 * w.ASS);
                ull nBa = fma2(V0, R3a, mul2(U0, R2a));
                ull nBb = fma2(V0, R3b, mul2(U0, R2b));
                ull nSa = fma2(V3, R3a, mul2(U3, R2a));
                ull nSb = fma2(V3, R3b, mul2(U3, R2b));
                ull nMa = fma2(V1, R1a, mul2(U1, R0a));
                ull nMb = fma2(V1, R1b, mul2(U1, R0b));
                ull nEa = fma2(V2, R1a, mul2(U2, R0a));
                ull nEb = fma2(V2, R1b, mul2(U2, R0b));
                R0a = nBa; R0b = nBb; R1a = nMa; R1b = nMb;
                R2a = nEa; R2b = nEb; R3a = nSa; R3b = nSb;
            }
        }
        float f0, f1, f2, f3, f4, f5, f6, f7, g0, g1, g2, g3, g4, g5, g6, g7;
        upk(R0a, f0, f1); upk(R0b, f2, f3); upk(R1a, f4, f5); upk(R1b, f6, f7);
        upk(R2a, g0, g1); upk(R2b, g2, g3); upk(R3a, g4, g5); upk(R3b, g6, g7);
        float mx = fmaxf(fmaxf(fmaxf(fmaxf(f0, f1), fmaxf(f2, f3)),
                               fmaxf(fmaxf(f4, f5), fmaxf(f6, f7))),
                         fmaxf(fmaxf(fmaxf(g0, g1), fmaxf(g2, g3)),
                               fmaxf(fmaxf(g4, g5), fmaxf(g6, g7))));
        int eb = __float_as_int(mx) >> 23;
        float sc = __int_as_float((254 - eb) << 23);
        c = fmaf((float)(eb - 127), LN2f, c);
        ull SC = pk2(sc);
        R0a = mul2(R0a, SC); R0b = mul2(R0b, SC);
        R1a = mul2(R1a, SC); R1b = mul2(R1b, SC);
        R2a = mul2(R2a, SC); R2b = mul2(R2b, SC);
        R3a = mul2(R3a, SC); R3b = mul2(R3b, SC);
    }
    float f0, f1, f2, f3;
    int b = ((k - 1) * 4) * N + seq;
    upk(R0a, f0, f1); upk(R0b, f2, f3); g_M[b]         = make_float4(f0, f1, f2, f3);
    upk(R1a, f0, f1); upk(R1b, f2, f3); g_M[b + N]     = make_float4(f0, f1, f2, f3);
    upk(R2a, f0, f1); upk(R2b, f2, f3); g_M[b + 2 * N] = make_float4(f0, f1, f2, f3);
    upk(R3a, f0, f1); upk(R3b, f2, f3); g_M[b + 3 * N] = make_float4(f0, f1, f2, f3);
    g_Mc[(k - 1) * N + seq] = c;
}

// ---------------- middle: compose 14 matvecs, 4 threads/seq, PINNED preload -
// thread = (seq, row). All 14 (row,cm) slots loaded up front and pinned via
// inline asm (ptxas cannot sink them); then pure compute chain.
__global__ __launch_bounds__(128) void mid_kernel(int N)
{
    int gt = blockIdx.x * 128 + threadIdx.x;
    if (gt >= 4 * N) return;
    const int seq = gt >> 2, row = gt & 3;
    const int gbase = (threadIdx.x & 31) & ~3;

    float4 RV[KM]; float CM[KM];
#pragma unroll
    for (int k = 0; k < KM; k++) {
        RV[k] = __ldg(&g_M[(size_t)(k * 4 + row) * N + seq]);
        CM[k] = __ldg(&g_Mc[(size_t)k * N + seq]);
    }
    // pin: forces all loads issued & values materialized before the chain
#pragma unroll
    for (int k = 0; k < KM; k++) {
        asm volatile("" : "+f"(RV[k].x), "+f"(RV[k].y), "+f"(RV[k].z),
                          "+f"(RV[k].w), "+f"(CM[k]));
    }

    float4 a = __ldg(&g_S[N + seq]);
    float c = fmaxf(fmaxf(a.x, a.y), fmaxf(a.z, a.w));
    float p0 = exp2f((a.x - c) * L2Ef), p1 = exp2f((a.y - c) * L2Ef);
    float p2 = exp2f((a.z - c) * L2Ef), p3 = exp2f((a.w - c) * L2Ef);

#pragma unroll
    for (int k = 1; k <= KM; k++) {
        float4 rv = RV[k - 1]; float cm = CM[k - 1];

        float q = fmaf(rv.x, p0, fmaf(rv.y, p1, fmaf(rv.z, p2, rv.w * p3)));
        float outv = fmaf(__log2f(q), LN2f, c + cm);     // own-row output, exact

        float q0 = __shfl_sync(0xFFFFFFFFu, q, gbase + 0);
        float q1 = __shfl_sync(0xFFFFFFFFu, q, gbase + 1);
        float q2 = __shfl_sync(0xFFFFFFFFu, q, gbase + 2);
        float q3 = __shfl_sync(0xFFFFFFFFu, q, gbase + 3);
        c += cm;
        float mx = fmaxf(fmaxf(q0, q1), fmaxf(q2, q3));
        int eb = __float_as_int(mx) >> 23;
        float sc = __int_as_float((254 - eb) << 23);
        c = fmaf((float)(eb - 127), LN2f, c);
        p0 = q0 * sc; p1 = q1 * sc; p2 = q2 * sc; p3 = q3 * sc;

        ((float*)g_S)[(size_t)(k + 1) * N * 4 + (size_t)seq * 4 + row] = outv;
    }
}

// ---------------- pass2: emit all alphas -----------------------------------
// block = 256 = 16 seqs x 16 chunks; warp = 2 seqs x 16 chunks.
// smem: bf16 table + per-warp u16 Y staging (stride-17 words, conflict-free).
__global__ __launch_bounds__(256, 3) void pass2_kernel(
    const int* __restrict__ Y, const float* __restrict__ mask,
    float* __restrict__ out, int N, int NV)
{
    extern __shared__ char sm2[];
    uint2* tab = (uint2*)sm2;
    unsigned* ysall = (unsigned*)(sm2 + (size_t)NV * 8);
    for (int i = threadIdx.x; i < NV; i += 256) tab[i] = g_BtH[i];
    __syncthreads();

    const int tid = threadIdx.x, lane = tid & 31, wid = tid >> 5;
    const int bseq = blockIdx.x * 16;
    const int seq  = bseq + (tid >> 4);
    const int k    = tid & 15;
    const int seqL = (tid >> 4) & 1;
    unsigned* ys = ysall + wid * 544;

    // stage Y (warp's 2 seqs x 512 t) as packed u16 pairs, coalesced loads
    {
        int sp0 = bseq + (wid << 1);
#pragma unroll
        for (int i = 0; i < 8; i++) {
            int sL = i >> 2, tb = (i & 3) * 128;
            int4 yv = __ldg((const int4*)(Y + (size_t)(sp0 + sL) * TT + tb) + lane);
            int kk = (i & 3) * 4 + (lane >> 3);
            int u2 = (lane & 7) * 2;
            ys[sL * 272 + kk * 17 + u2]     = (unsigned)yv.x | ((unsigned)yv.y << 16);
            ys[sL * 272 + kk * 17 + u2 + 1] = (unsigned)yv.z | ((unsigned)yv.w << 16);
        }
    }
    __syncwarp();

    W8 w = load_wc();
    unsigned mb = g_mb[(size_t)bseq * 16 + tid];   // == g_mb[seq*16 + k]

    float4 a = __ldg(&g_S[k * N + seq]);           // exact start (alpha0 for k=0)
    float ap0 = a.x, ap1 = a.y, ap2 = a.z, ap3 = a.w;
    float c  = fmaxf(fmaxf(ap0, ap1), fmaxf(ap2, ap3));
    float p0 = exp2f((ap0 - c) * L2Ef), p1 = exp2f((ap1 - c) * L2Ef);
    float p2 = exp2f((ap2 - c) * L2Ef), p3 = exp2f((ap3 - c) * L2Ef);

    const unsigned* ysk = ys + seqL * 272 + k * 17;
    float* rowp = out + (size_t)seq * (4 * TT) + k * 32;

#pragma unroll 1
    for (int g = 0; g < 4; g++) {
        float4 an[8];
#pragma unroll
        for (int h = 0; h < 2; h++) {
            int j0 = g * 8 + h * 4;
            unsigned w0 = ysk[(j0 >> 1)];
            unsigned w1 = ysk[(j0 >> 1) + 1];
            uint2 evs[4];
            evs[0] = tab[w0 & 0xFFFFu]; evs[1] = tab[w0 >> 16];
            evs[2] = tab[w1 & 0xFFFFu]; evs[3] = tab[w1 >> 16];
#pragma unroll
            for (int q = 0; q < 4; q++) {
                int j = j0 + q;
                if (k == 0 && j == 0 && g == 0) {
                    an[0] = make_float4(ap0, ap1, ap2, ap3);   // t=0 exact
                } else {
                    float e0, e1, e2, e3; unp(evs[q], e0, e1, e2, e3);
                    float qB = e0 * fmaf(w.ASB, p3, w.AEB * p2);
                    float qM = e1 * fmaf(w.AMM, p1, w.ABM * p0);
                    float qE = e2 * fmaf(w.AME, p1, w.ABE * p0);
                    float qS = e3 * fmaf(w.ASS, p3, w.AES * p2);
                    float n0 = fmaf(__log2f(qB), LN2f, c);
                    float n1 = fmaf(__log2f(qM), LN2f, c);
                    float n2 = fmaf(__log2f(qE), LN2f, c);
                    float n3 = fmaf(__log2f(qS), LN2f, c);
                    if ((mb >> j) & 1u) {
                        p0 = qB; p1 = qM; p2 = qE; p3 = qS;
                        if (q == 3) {
                            float mx = fmaxf(fmaxf(p0, p1), fmaxf(p2, p3));
                            int eb = __float_as_int(mx) >> 23;
                            float sc = __int_as_float((254 - eb) << 23);
                            c = fmaf((float)(eb - 127), LN2f, c);
                            p0 *= sc; p1 *= sc; p2 *= sc; p3 *= sc;
                        }
                    } else {
                        // rare general path: fetch float mask, exact blend
                        float m = __ldg(&mask[(size_t)seq * TT + k * 32 + j]);
                        n0 = fmaf(m, n0 - ap0, ap0);
                        n1 = fmaf(m, n1 - ap1, ap1);
                        n2 = fmaf(m, n2 - ap2, ap2);
                        n3 = fmaf(m, n3 - ap3, ap3);
                        c  = fmaxf(fmaxf(n0, n1), fmaxf(n2, n3));
                        p0 = exp2f((n0 - c) * L2Ef); p1 = exp2f((n1 - c) * L2Ef);
                        p2 = exp2f((n2 - c) * L2Ef); p3 = exp2f((n3 - c) * L2Ef);
                    }
                    ap0 = n0; ap1 = n1; ap2 = n2; ap3 = n3;
                    an[j - g * 8] = make_float4(n0, n1, n2, n3);
                }
            }
        }
        // direct stores: per state a full 32B sector (two aligned STG.128)
        float* gp = rowp + g * 8;
        *(float4*)(gp)               = make_float4(an[0].x, an[1].x, an[2].x, an[3].x);
        *(float4*)(gp + 4)           = make_float4(an[4].x, an[5].x, an[6].x, an[7].x);
        *(float4*)(gp + TT)          = make_float4(an[0].y, an[1].y, an[2].y, an[3].y);
        *(float4*)(gp + TT + 4)      = make_float4(an[4].y, an[5].y, an[6].y, an[7].y);
        *(float4*)(gp + 2 * TT)      = make_float4(an[0].z, an[1].z, an[2].z, an[3].z);
        *(float4*)(gp + 2 * TT + 4)  = make_float4(an[4].z, an[5].z, an[6].z, an[7].z);
        *(float4*)(gp + 3 * TT)      = make_float4(an[0].w, an[1].w, an[2].w, an[3].w);
        *(float4*)(gp + 3 * TT + 4)  = make_float4(an[4].w, an[5].w, an[6].w, an[7].w);
    }
}

extern "C" void kernel_launch(void* const* d_in, const int* in_sizes, int n_in,
                              void* d_out, int out_size) {
    const int*   Y     = (const int*)  d_in[0];
    const float* mask  = (const float*)d_in[1];
    const float* logpi = (const float*)d_in[2];
    const float* logA  = (const float*)d_in[3];
    const float* logB  = (const float*)d_in[4];
    float*       out   = (float*)d_out;

    const int N  = in_sizes[0] / TT;
    const int NV = in_sizes[4] / 4;

    const int smem1 = NV * 8 + 8 * 544 * 4;         // 65408 B (table + Y staging)
    const int smem2 = NV * 8 + 8 * 544 * 4;         // 65408 B (table + Y staging)

    cudaFuncSetAttribute(pass1_kernel, cudaFuncAttributeMaxDynamicSharedMemorySize, smem1);
    cudaFuncSetAttribute(pass2_kernel, cudaFuncAttributeMaxDynamicSharedMemorySize, smem2);

    prep_kernel<<<(NV + 255) / 256, 256>>>(logB, logA, logpi, NV);
    prep_bits_kernel<<<N / 16, 256>>>(mask, N);
    pass1_kernel<<<((KM + 1) * N + 255) / 256, 256, smem1>>>(Y, logB, N, NV);
    mid_kernel<<<(4 * N + 127) / 128, 128>>>(N);
    pass2_kernel<<<N / 16, 256, smem2>>>(Y, mask, out, N, NV);
}